// round 15
// baseline (speedup 1.0000x reference)
#include <cuda_runtime.h>
#include <cstdint>

// Problem dims
#define BB 4
#define MM 512
#define NN 512
#define KK 128

// Decoded scratch, k-major per batch: g_dA[b][k][m], g_dB[b][k][n]
__device__ __align__(16) float g_dA[BB * KK * MM];
__device__ __align__(16) float g_dB[BB * KK * NN];

// ---------------------------------------------------------------------------
// Kernel 1: decode 8-pulse FP8 E4M3 codes -> fp32, k-major output via smem
// transpose. K-SPLIT grid: each CTA does 8 rows x 64 k -> 1024 CTAs (~7/SM)
// for MLP (R7/R13: 512 CTAs left decode latency-bound at occ 41%).
// Keeps 32B-per-k-row write granularity (full sectors) and 2KB/row coalesced
// input reads. Exact decode: power-of-two via exponent field; (1+m/8) exact.
// ---------------------------------------------------------------------------
#define DEC_R 8
#define DEC_K 64

__global__ __launch_bounds__(256) void decode_kernel(const float4* __restrict__ inA,
                                                     const float4* __restrict__ inB) {
    __shared__ float s[DEC_K][DEC_R + 1];  // [k][r], pad -> conflict-free

    const int blk = blockIdx.x;                 // 0..1023
    const bool isB = blk >= 512;
    const int sub = isB ? (blk - 512) : blk;    // 0..511
    const int b   = sub >> 7;                   // batch 0..3
    const int rem = sub & 127;                  // 64 row-blocks x 2 k-halves
    const int r0  = (rem >> 1) * DEC_R;         // row-block start
    const int k0  = (rem & 1) * DEC_K;          // k-half start

    const float4* __restrict__ in = isB ? inB : inA;
    float* __restrict__ outp = isB ? g_dB : g_dA;

    const int tid = threadIdx.x;

    // Decode 2 codes per thread; 512 codes = 8 rows x 64 k.
    // c: r = c>>6, kk = c&63. Input contiguous per row (64 codes x 32B).
#pragma unroll
    for (int j = 0; j < 2; j++) {
        int c  = j * 256 + tid;          // 0..511
        int r  = c >> 6;
        int kk = c & (DEC_K - 1);
        long ci = ((long)(b * MM + r0 + r)) * KK + k0 + kk;
        float4 p0 = in[ci * 2];
        float4 p1 = in[ci * 2 + 1];

        float ef = p0.y * 8.0f + p0.z * 4.0f + p0.w * 2.0f + p1.x;
        float mf = p1.y * 4.0f + p1.z * 2.0f + p1.w;
        int e = (int)ef;

        float mag;
        if (e > 0) {
            mag = __uint_as_float((unsigned)(e + 120) << 23) * (1.0f + mf * 0.125f);
        } else {
            mag = mf * (1.0f / 512.0f);  // subnormal: m * 2^-9
        }
        float val = (p0.x > 0.5f) ? -mag : mag;

        s[kk][r] = val;
    }
    __syncthreads();

    // Write k-major: 64 k-rows x 2 float4 = 128 float4; threads 0..127.
    // 32B contiguous per k-row (full sectors).
    if (tid < 128) {
        int k  = tid >> 1;
        int r4 = (tid & 1) * 4;
        float4 v;
        v.x = s[k][r4 + 0];
        v.y = s[k][r4 + 1];
        v.z = s[k][r4 + 2];
        v.w = s[k][r4 + 3];
        *(float4*)&outp[(b * KK + k0 + k) * MM + r0 + r4] = v;
    }
}

// ---------------------------------------------------------------------------
// Kernel 2: FUSED batched GEMM + bit-plane encode (R13 body, byte-identical:
// best measured variant, 29.0us).
// 64x32 C tile per CTA (grid=512, 4 CTAs/SM -> ONE wave), 256 threads,
// 4x2 micro-tile: per k, 1 LDS.128 (A, broadcast) + 1 LDS.64 (B) feeds 8 FMA.
// STRICT sequential-k fp32 FMA accumulation (single accumulator per element,
// k=0..127 ascending, one term per k) -- DO NOT reassociate; bit-exactness
// vs reference depends on this.
// Encode: stage C in smem, lane-contiguous STG.128 with __stcs.
// ---------------------------------------------------------------------------
#define BMT 64
#define BNT 32

__global__ __launch_bounds__(256, 4) void gemm_encode_kernel(float4* __restrict__ out) {
    __shared__ float As[KK][BMT];   // 32 KB, k-major [k][m]
    __shared__ float Bs[KK][BNT];   // 16 KB, k-major [k][n]

    const int b   = blockIdx.z;
    const int tm0 = blockIdx.y * BMT;
    const int tn0 = blockIdx.x * BNT;
    const int tid = threadIdx.x;
    const int tx  = tid & 15;        // n selector: cols tx*2, tx*2+1
    const int ty  = tid >> 4;        // m selector: rows ty*4 .. ty*4+3

    const float* __restrict__ Ab = g_dA + b * KK * MM;
    const float* __restrict__ Bb = g_dB + b * KK * NN;

    // Load full-K tiles: A 128x64 (8 float4/thread), B 128x32 (4/thread).
#pragma unroll
    for (int i = 0; i < 8; i++) {
        int w  = i * 256 + tid;
        int r  = w >> 4;              // k row 0..127
        int c4 = (w & 15) * 4;        // m offset
        *(float4*)&As[r][c4] = *(const float4*)&Ab[r * MM + tm0 + c4];
    }
#pragma unroll
    for (int i = 0; i < 4; i++) {
        int w  = i * 256 + tid;
        int r  = w >> 3;              // k row 0..127
        int c4 = (w & 7) * 4;         // n offset
        *(float4*)&Bs[r][c4] = *(const float4*)&Bb[r * NN + tn0 + c4];
    }
    __syncthreads();

    float acc[4][2];
#pragma unroll
    for (int i = 0; i < 4; i++) { acc[i][0] = 0.0f; acc[i][1] = 0.0f; }

    // Sequential over k (ascending), single accumulator per element.
#pragma unroll 16
    for (int k = 0; k < KK; k++) {
        float4 a4 = *(const float4*)&As[k][ty * 4];
        float2 b2 = *(const float2*)&Bs[k][tx * 2];
        acc[0][0] = fmaf(a4.x, b2.x, acc[0][0]);
        acc[0][1] = fmaf(a4.x, b2.y, acc[0][1]);
        acc[1][0] = fmaf(a4.y, b2.x, acc[1][0]);
        acc[1][1] = fmaf(a4.y, b2.y, acc[1][1]);
        acc[2][0] = fmaf(a4.z, b2.x, acc[2][0]);
        acc[2][1] = fmaf(a4.z, b2.y, acc[2][1]);
        acc[3][0] = fmaf(a4.w, b2.x, acc[3][0]);
        acc[3][1] = fmaf(a4.w, b2.y, acc[3][1]);
    }
    __syncthreads();  // all reads of As done before reuse as Cs

    // Stage C tile into smem: Cs[64][32] overlaid on As.
    float* Cs = &As[0][0];
#pragma unroll
    for (int i = 0; i < 4; i++) {
        *(float2*)&Cs[(ty * 4 + i) * BNT + tx * 2] = make_float2(acc[i][0], acc[i][1]);
    }
    __syncthreads();

    // Encode + store: tile covers 256 contiguous float4 per output row, 64 rows.
    // Thread t: n_local = t>>3, nibble q = t&7; lanes contiguous (512B/warp).
    const unsigned base0 = ((unsigned)((b * MM + tm0) * NN + tn0)) * 8u;
    const unsigned q  = (unsigned)(tid & 7);
    const unsigned s0 = 28u - 4u * q;        // bit pos of .w
    const int nl = tid >> 3;

#pragma unroll 4
    for (int ml = 0; ml < BMT; ml++) {
        unsigned u = __float_as_uint(Cs[ml * BNT + nl]);
        float4 v;
        v.x = ((u >> (s0 + 3)) & 1u) ? 1.0f : 0.0f;
        v.y = ((u >> (s0 + 2)) & 1u) ? 1.0f : 0.0f;
        v.z = ((u >> (s0 + 1)) & 1u) ? 1.0f : 0.0f;
        v.w = ((u >> (s0 + 0)) & 1u) ? 1.0f : 0.0f;
        __stcs(&out[base0 + (unsigned)ml * (NN * 8u) + (unsigned)tid], v);
    }
}

extern "C" void kernel_launch(void* const* d_in, const int* in_sizes, int n_in,
                              void* d_out, int out_size) {
    const float4* A = (const float4*)d_in[0];
    const float4* B = (const float4*)d_in[1];

    decode_kernel<<<1024, 256>>>(A, B);

    dim3 grid(NN / BNT, MM / BMT, BB);  // (16, 8, 4) = 512 CTAs
    gemm_encode_kernel<<<grid, 256>>>((float4*)d_out);
}

// round 16
// speedup vs baseline: 1.0604x; 1.0604x over previous
#include <cuda_runtime.h>
#include <cstdint>

// Problem dims
#define BB 4
#define MM 512
#define NN 512
#define KK 128

// Decoded scratch, k-major per batch: g_dA[b][k][m], g_dB[b][k][n]
__device__ __align__(16) float g_dA[BB * KK * MM];
__device__ __align__(16) float g_dB[BB * KK * NN];

// ---------------------------------------------------------------------------
// Kernel 1: decode 8-pulse FP8 E4M3 codes -> fp32, k-major output via smem
// transpose. Proven R7 config: 256 threads, DEC_R=8, grid=512 (6.9us).
// (R15 showed k-splitting to 1024 CTAs is MLP-neutral; reverted.)
// Exact decode: power-of-two via exponent field; (1+m/8) exact.
// ---------------------------------------------------------------------------
#define DEC_R 8

__global__ __launch_bounds__(256) void decode_kernel(const float4* __restrict__ inA,
                                                     const float4* __restrict__ inB) {
    __shared__ float s[KK][DEC_R + 1];  // pad -> conflict-free

    const int blk = blockIdx.x;                 // 0..511
    const bool isB = blk >= 256;
    const int sub = isB ? (blk - 256) : blk;    // 0..255
    const int b  = sub >> 6;                    // batch (64 row-blocks/batch)
    const int r0 = (sub & 63) * DEC_R;          // row-block start

    const float4* __restrict__ in = isB ? inB : inA;
    float* __restrict__ outp = isB ? g_dB : g_dA;

    const int tid = threadIdx.x;
    const long gbase = ((long)(b * MM + r0)) * KK;

#pragma unroll
    for (int j = 0; j < 4; j++) {
        int c = j * 256 + tid;           // r_local = c>>7, k = c&127
        float4 p0 = in[(gbase + c) * 2];
        float4 p1 = in[(gbase + c) * 2 + 1];

        float ef = p0.y * 8.0f + p0.z * 4.0f + p0.w * 2.0f + p1.x;
        float mf = p1.y * 4.0f + p1.z * 2.0f + p1.w;
        int e = (int)ef;

        float mag;
        if (e > 0) {
            mag = __uint_as_float((unsigned)(e + 120) << 23) * (1.0f + mf * 0.125f);
        } else {
            mag = mf * (1.0f / 512.0f);  // subnormal: m * 2^-9
        }
        float val = (p0.x > 0.5f) ? -mag : mag;

        s[c & (KK - 1)][c >> 7] = val;
    }
    __syncthreads();

    {
        int k  = tid >> 1;
        int r4 = (tid & 1) * 4;
        float4 v;
        v.x = s[k][r4 + 0];
        v.y = s[k][r4 + 1];
        v.z = s[k][r4 + 2];
        v.w = s[k][r4 + 3];
        *(float4*)&outp[(b * KK + k) * MM + r0 + r4] = v;
    }
}

// ---------------------------------------------------------------------------
// Kernel 2: FUSED batched GEMM + bit-plane encode, WARP-LOCAL EPILOGUE.
// 64x32 C tile per CTA (grid=512, 4 CTAs/SM -> ONE wave), 256 threads,
// 4x2 micro-tile (identical compute/indexing to R13: ro=tid>>4, nx=tid&15).
// Warp w's lanes compute exactly C rows [8w, 8w+8), so after the k-loop each
// warp stages its OWN 8x32 slice into a private padded smem buffer and
// encodes/stores its own rows with only a __syncwarp -- NO CTA barrier after
// compute. Warps drift into the store stream independently -> phase overlap.
// STRICT sequential-k fp32 FMA accumulation (single accumulator per element,
// k=0..127 ascending, one term per k) -- DO NOT reassociate; bit-exactness
// vs reference depends on this.
// Dynamic smem (56.25KB > 48KB static limit); attribute set in static ctor.
// ---------------------------------------------------------------------------
#define BMT 64
#define BNT 32
#define CWS 33   // padded row stride of the per-warp C slices
#define SMEM_FLOATS (KK * BMT + KK * BNT + 64 * CWS)   // 8192+4096+2112
#define SMEM_BYTES  (SMEM_FLOATS * 4)                   // 57600

__global__ __launch_bounds__(256, 4) void gemm_encode_kernel(float4* __restrict__ out) {
    extern __shared__ float sm[];
    float* As = sm;                      // [128][64], As[k*64+m]
    float* Bs = sm + KK * BMT;           // [128][32], Bs[k*32+n]
    float* Cw = sm + KK * BMT + KK * BNT;  // [64][CWS]: (w*8+r)*CWS + n

    const int b   = blockIdx.z;
    const int tm0 = blockIdx.y * BMT;
    const int tn0 = blockIdx.x * BNT;
    const int tid = threadIdx.x;
    const int nx  = tid & 15;        // n selector: cols nx*2, nx*2+1
    const int ro  = tid >> 4;        // m selector: rows ro*4 .. ro*4+3
    const int w   = tid >> 5;        // warp id: owns C rows [8w, 8w+8)
    const int lane = tid & 31;
    const int my  = (tid >> 4) & 1;  // ro = w*2 + my

    const float* __restrict__ Ab = g_dA + b * KK * MM;
    const float* __restrict__ Bb = g_dB + b * KK * NN;

    // Load full-K tiles: A 128x64 (8 float4/thread), B 128x32 (4/thread).
#pragma unroll
    for (int i = 0; i < 8; i++) {
        int v  = i * 256 + tid;
        int r  = v >> 4;              // k row 0..127
        int c4 = (v & 15) * 4;        // m offset
        *(float4*)&As[r * BMT + c4] = *(const float4*)&Ab[r * MM + tm0 + c4];
    }
#pragma unroll
    for (int i = 0; i < 4; i++) {
        int v  = i * 256 + tid;
        int r  = v >> 3;              // k row 0..127
        int c4 = (v & 7) * 4;         // n offset
        *(float4*)&Bs[r * BNT + c4] = *(const float4*)&Bb[r * NN + tn0 + c4];
    }
    __syncthreads();

    float acc[4][2];
#pragma unroll
    for (int i = 0; i < 4; i++) { acc[i][0] = 0.0f; acc[i][1] = 0.0f; }

    // Sequential over k (ascending), single accumulator per element.
#pragma unroll 16
    for (int k = 0; k < KK; k++) {
        float4 a4 = *(const float4*)&As[k * BMT + ro * 4];
        float2 b2 = *(const float2*)&Bs[k * BNT + nx * 2];
        acc[0][0] = fmaf(a4.x, b2.x, acc[0][0]);
        acc[0][1] = fmaf(a4.x, b2.y, acc[0][1]);
        acc[1][0] = fmaf(a4.y, b2.x, acc[1][0]);
        acc[1][1] = fmaf(a4.y, b2.y, acc[1][1]);
        acc[2][0] = fmaf(a4.z, b2.x, acc[2][0]);
        acc[2][1] = fmaf(a4.z, b2.y, acc[2][1]);
        acc[3][0] = fmaf(a4.w, b2.x, acc[3][0]);
        acc[3][1] = fmaf(a4.w, b2.y, acc[3][1]);
    }

    // Warp-local staging: rows r_loc = my*4+i (0..7 within warp's slice).
#pragma unroll
    for (int i = 0; i < 4; i++) {
        int r_loc = my * 4 + i;
        Cw[(w * 8 + r_loc) * CWS + nx * 2 + 0] = acc[i][0];
        Cw[(w * 8 + r_loc) * CWS + nx * 2 + 1] = acc[i][1];
    }
    __syncwarp();

    // Warp-local encode + store of rows [8w, 8w+8).
    // f4 index within row segment = c*32 + lane: n_local = c*4 + (lane>>3),
    // nibble q = lane&7. Warp stores 512B contiguous per STG.128.
    const int g = lane >> 3;
    const unsigned q  = (unsigned)(lane & 7);
    const unsigned s0 = 28u - 4u * q;        // bit pos of .w

#pragma unroll
    for (int r = 0; r < 8; r++) {
        const unsigned base_r =
            ((unsigned)((b * MM + tm0 + w * 8 + r) * NN + tn0)) * 8u;
        const float* crow = &Cw[(w * 8 + r) * CWS];
#pragma unroll
        for (int c = 0; c < 8; c++) {
            unsigned u = __float_as_uint(crow[c * 4 + g]);
            float4 v;
            v.x = ((u >> (s0 + 3)) & 1u) ? 1.0f : 0.0f;
            v.y = ((u >> (s0 + 2)) & 1u) ? 1.0f : 0.0f;
            v.z = ((u >> (s0 + 1)) & 1u) ? 1.0f : 0.0f;
            v.w = ((u >> (s0 + 0)) & 1u) ? 1.0f : 0.0f;
            __stcs(&out[base_r + (unsigned)(c * 32 + lane)], v);
        }
    }
}

// Set dynamic-smem limit once at module init (NOT during graph capture).
namespace {
struct _SmemInit {
    _SmemInit() {
        cudaFuncSetAttribute(gemm_encode_kernel,
                             cudaFuncAttributeMaxDynamicSharedMemorySize,
                             SMEM_BYTES);
    }
};
_SmemInit _smem_init;
}

extern "C" void kernel_launch(void* const* d_in, const int* in_sizes, int n_in,
                              void* d_out, int out_size) {
    const float4* A = (const float4*)d_in[0];
    const float4* B = (const float4*)d_in[1];

    decode_kernel<<<512, 256>>>(A, B);

    dim3 grid(NN / BNT, MM / BMT, BB);  // (16, 8, 4) = 512 CTAs
    gemm_encode_kernel<<<grid, 256, SMEM_BYTES>>>((float4*)d_out);
}